// round 9
// baseline (speedup 1.0000x reference)
#include <cuda_runtime.h>

// ---------------------------------------------------------------------------
// PCritical step, B=32, N=4096 — warp-specialized fused pass over W.
// Producers (warps 0-7) stream W tiles (DRAM); consumers (warps 8-15) run both
// binary-S GEMMs from smem (LDS) one stage behind, double-buffered.
// Outputs concatenated float32 in reference return order:
//   S (B,N) | mem_pot_n (B,N) | W_new (N,N) | mem_cur_n (B,N) |
//   mem_pot_p_n (B,N) | mem_cur_p_n (B,N) | refrac_new (B,N)
// ---------------------------------------------------------------------------

#define Bsz 32
#define Nsz 4096
#define BN  (Bsz * Nsz)        // 131072
#define NN  (Nsz * Nsz)        // 16777216

#define C_ALPHA 0.025f
#define C_BETA  0.00025f
#define C_TNOW  10.0f
#define C_INV_TAU_V 0.9801986733067553f
#define C_INV_TAU_I 0.36787944117144233f

#define OUT_S    ((long long)0)
#define OUT_POT  ((long long)BN)
#define OUT_W    ((long long)(2LL * BN))
#define OUT_CUR  ((long long)(2LL * BN + NN))
#define OUT_POTP ((long long)(3LL * BN + NN))
#define OUT_CURP ((long long)(4LL * BN + NN))
#define OUT_REFR ((long long)(5LL * BN + NN))

#define JBLK   32              // grid.x: 4096/128 column chunks
#define IBLK   4               // grid.y: row super-chunks (1024 rows)
#define NST    8               // stages per block (1024/128)
#define PITCH  129             // 129 ≡ 1 (mod 32): rows AND cols conflict-free
#define TILE_F (128 * PITCH)   // floats per tile buffer (16512)

// scratch (no dynamic allocation allowed)
__device__ __align__(16) unsigned g_masks[Nsz];          // bit b <=> S[b,n]==1
__device__ __align__(16) float    g_e[Nsz];
__device__ __align__(16) float    g_ie[Nsz];
__device__ __align__(16) float    g_A[Nsz];              // sp ? ALPHA*e  : 0
__device__ __align__(16) float    g_Ai[Nsz];             // sp ? ALPHA*ie : 0
__device__ __align__(16) float    g_accP[IBLK * BN];     // partials S@W_new
__device__ __align__(16) float    g_accTP[JBLK * BN];    // partials S@W_new^T

// ---------------------------------------------------------------------------
// K1: per-neuron batch reductions + exp precompute (4-way batch split).
// ---------------------------------------------------------------------------
__global__ void __launch_bounds__(128) k_prologue(
    const float* __restrict__ mem_pot,
    const float* __restrict__ mem_pot_paired,
    const float* __restrict__ st)
{
    int gid = blockIdx.x * 128 + threadIdx.x;   // 4*Nsz threads
    int n = gid >> 2;
    int q = gid & 3;
    int b0 = q * 8;

    unsigned mp_ = 0u;
    bool anyp = false;
#pragma unroll
    for (int k = 0; k < 8; ++k) {
        int b = b0 + k;
        float mp = mem_pot[b * Nsz + n];
        if (mp > 1.0f) mp_ |= (1u << b);
        float mpp = mem_pot_paired[b * Nsz + n];
        if (((mpp - 1.0f) - C_ALPHA) > 0.0f) anyp = true;
    }
    mp_ |= __shfl_xor_sync(0xffffffffu, mp_, 1);
    anyp = anyp | (bool)__shfl_xor_sync(0xffffffffu, (int)anyp, 1);
    mp_ |= __shfl_xor_sync(0xffffffffu, mp_, 2);
    anyp = anyp | (bool)__shfl_xor_sync(0xffffffffu, (int)anyp, 2);

    if (q == 0) {
        unsigned m = mp_;
        float stn = st[n];
        float maxst = (m == 0xffffffffu) ? C_TNOW
                    : (m ? fmaxf(C_TNOW, stn) : stn);
        float e  = expf(maxst * (1.0f / 50.0f));
        float ie = expf(-maxst * (1.0f / 50.0f));
        g_masks[n] = m;
        g_e[n]  = e;
        g_ie[n] = ie;
        g_A[n]  = anyp ? C_ALPHA * e  : 0.0f;
        g_Ai[n] = anyp ? C_ALPHA * ie : 0.0f;
    }
}

__device__ __forceinline__ float upd1(float w, float A, float Ai, float e, float ie)
{
    float sub = fmaxf(A * ie, Ai * e);        // 0 when row not paired-spiking
    float u = (w + C_BETA) - sub;
    u = fminf(fmaxf(u, 0.0f), 1.0f);
    return (w > 0.0f) ? u : w;                // sign_mask = W_rec > 0
}

// ---------------------------------------------------------------------------
// K2: warp-specialized fused kernel. 128 blocks x 512 threads, 1 block/SM.
// ---------------------------------------------------------------------------
__global__ void __launch_bounds__(512, 1) k_fused(
    const float* __restrict__ W, float* __restrict__ Wout)
{
    extern __shared__ float sm[];
    // [0)            buf0 tile (128x129)
    // [TILE_F)       buf1 tile
    // [2*TILE_F)     rbj[32][4]   transposed col masks (128 words)
    //                rbi[32][32]  transposed row masks, all 1024 rows
    unsigned* rbj = (unsigned*)(sm + 2 * TILE_F);
    unsigned* rbi = rbj + 128;

    const int jc   = blockIdx.x;       // 0..31
    const int ib   = blockIdx.y;       // 0..3
    const int warp = threadIdx.x >> 5; // 0..15
    const int lane = threadIdx.x & 31;
    const int jg0  = jc * 128;
    const int ig00 = ib * 1024;
    const bool producer = (warp < 8);

    if (producer) {
        // ---------------- PRODUCER ----------------
        // warp owns rows [warp*16, warp*16+16) of each stage; lane owns 4 cols.
        const int j4 = lane * 4;
        float4 e4  = *(const float4*)(g_e  + jg0 + j4);
        float4 ie4 = *(const float4*)(g_ie + jg0 + j4);

        // produce(stage s) into buf[s&1]
        for (int s = 0; s <= NST; ++s) {
            if (s < NST) {
                const int ig0 = ig00 + s * 128;
                float* buf = sm + (s & 1) * TILE_F;
#pragma unroll
                for (int rr = 0; rr < 2; ++rr) {
                    float4 v[8];
                    const int ilb = warp * 16 + rr * 8;
#pragma unroll
                    for (int r = 0; r < 8; ++r)
                        v[r] = *(const float4*)(W + (size_t)(ig0 + ilb + r) * Nsz + jg0 + j4);
#pragma unroll
                    for (int r = 0; r < 8; ++r) {
                        int il = ilb + r;
                        int ig = ig0 + il;
                        float A  = g_A[ig];
                        float Ai = g_Ai[ig];
                        float4 u;
                        u.x = upd1(v[r].x, A, Ai, e4.x, ie4.x);
                        u.y = upd1(v[r].y, A, Ai, e4.y, ie4.y);
                        u.z = upd1(v[r].z, A, Ai, e4.z, ie4.z);
                        u.w = upd1(v[r].w, A, Ai, e4.w, ie4.w);
                        *(float4*)(Wout + (size_t)ig * Nsz + jg0 + j4) = u;
                        float* cr = buf + il * PITCH + j4;   // scalar STS (pitch 129)
                        cr[0] = u.x; cr[1] = u.y; cr[2] = u.z; cr[3] = u.w;
                    }
                }
            }
            __syncthreads();   // stage boundary (matched by consumers)
        }
    } else {
        // ---------------- CONSUMER ----------------
        const int cw = warp - 8;        // 0..7; owns batches cw*4 .. cw*4+3

        // mask transposes: 32 row-groups (all 8 stages) + 4 col-groups,
        // overlapped with producers filling stage 0.
        for (int g = cw; g < 36; g += 8) {
            unsigned mw = (g < 32) ? g_masks[ig00 + g * 32 + lane]
                                   : g_masks[jg0 + (g - 32) * 32 + lane];
#pragma unroll
            for (int b = 0; b < 32; ++b) {
                unsigned w = __ballot_sync(0xffffffffu, (mw >> b) & 1u);
                if (lane == b) {
                    if (g < 32) rbi[b * 32 + g] = w;
                    else        rbj[b * 4 + (g - 32)] = w;
                }
            }
        }
        __syncthreads();   // stage 0 ready

        // Phase-B accumulators: 4 batches x 4 j-slots, persist across stages
        float aB[4][4];
#pragma unroll
        for (int k = 0; k < 4; ++k)
#pragma unroll
            for (int x = 0; x < 4; ++x) aB[k][x] = 0.0f;

        const int lp = lane * PITCH;

        for (int s = 0; s < NST; ++s) {
            const float* buf = sm + (s & 1) * TILE_F;

            // ---- Phase B: acc[b][j] over active rows of stage s ----
#pragma unroll
            for (int k = 0; k < 4; ++k) {
                const int b = cw * 4 + k;
#pragma unroll
                for (int q = 0; q < 4; ++q) {
                    unsigned m = rbi[b * 32 + s * 4 + q];
                    while (m) {
                        int r = q * 32 + __ffs(m) - 1; m &= m - 1;
                        const float* cr = buf + r * PITCH;
                        aB[k][0] += cr[lane];
                        aB[k][1] += cr[lane + 32];
                        aB[k][2] += cr[lane + 64];
                        aB[k][3] += cr[lane + 96];
                    }
                }
            }

            // ---- Phase C: accT[b][i] over active cols of stage s ----
#pragma unroll
            for (int k = 0; k < 4; ++k) {
                const int b = cw * 4 + k;
                float t0 = 0, t1 = 0, t2 = 0, t3 = 0;
#pragma unroll
                for (int q = 0; q < 4; ++q) {
                    unsigned m = rbj[b * 4 + q];
                    while (m) {
                        int j = q * 32 + __ffs(m) - 1; m &= m - 1;
                        const float* cc = buf + j + lp;
                        t0 += cc[0];
                        t1 += cc[32 * PITCH];
                        t2 += cc[64 * PITCH];
                        t3 += cc[96 * PITCH];
                    }
                }
                size_t o = ((size_t)jc * Bsz + b) * Nsz + ig00 + s * 128 + lane;
                g_accTP[o]      = t0;
                g_accTP[o + 32] = t1;
                g_accTP[o + 64] = t2;
                g_accTP[o + 96] = t3;
            }
            __syncthreads();   // stage boundary (matched by producers)
        }

        // write Phase-B partials (one per ib super-chunk)
#pragma unroll
        for (int k = 0; k < 4; ++k) {
            const int b = cw * 4 + k;
            size_t o = ((size_t)ib * Bsz + b) * Nsz + jg0 + lane;
            g_accP[o]      = aB[k][0];
            g_accP[o + 32] = aB[k][1];
            g_accP[o + 64] = aB[k][2];
            g_accP[o + 96] = aB[k][3];
        }
    }
}

// ---------------------------------------------------------------------------
// K3: epilogue — reduce partials, integrate, leak, reset, refractory
// ---------------------------------------------------------------------------
__global__ void __launch_bounds__(256) k_epilogue(
    const float* __restrict__ inp,
    const float* __restrict__ mem_pot,
    const float* __restrict__ mem_cur,
    const float* __restrict__ mem_pot_paired,
    const float* __restrict__ mem_cur_paired,
    const int*   __restrict__ refrac,
    float* __restrict__ out)
{
    int t = blockIdx.x * 256 + threadIdx.x;   // BN threads
    int b = t >> 12;
    int n = t & (Nsz - 1);

    float acc = 0.0f;
#pragma unroll
    for (int cN = 0; cN < IBLK; ++cN) acc += g_accP[(size_t)cN * BN + t];
    float accT = 0.0f;
#pragma unroll
    for (int cN = 0; cN < JBLK; ++cN) accT += g_accTP[(size_t)cN * BN + t];

    int r  = refrac[t];
    int rd = (r > 0) ? (r - 1) : r;
    bool active = (rd == 0);

    unsigned m = g_masks[n];
    bool s  = ((m >> b) & 1u) != 0u;
    float mppv = mem_pot_paired[t];
    bool sp = ((mppv - 1.0f) - C_ALPHA) > 0.0f;

    float mp   = mem_pot[t];
    float mc   = mem_cur[t];
    float mcpv = mem_cur_paired[t];

    float mcn  = active ? (inp[t] + acc) + mc : mc;
    float mcpn = active ? accT + mcpv : mcpv;
    float mpn  = active ? mcn + mp : mp;
    float mppn = active ? mcpn + mppv : mppv;

    mpn  *= C_INV_TAU_V;
    mcn  *= C_INV_TAU_I;
    mppn *= C_INV_TAU_V;
    mcpn *= C_INV_TAU_I;

    if (s)  mpn  = 0.0f;
    if (sp) mppn = 0.0f;
    float rn = s ? 2.0f : (float)rd;

    out[OUT_S    + t] = s ? 1.0f : 0.0f;
    out[OUT_POT  + t] = mpn;
    out[OUT_CUR  + t] = mcn;
    out[OUT_POTP + t] = mppn;
    out[OUT_CURP + t] = mcpn;
    out[OUT_REFR + t] = rn;
}

// ---------------------------------------------------------------------------
extern "C" void kernel_launch(void* const* d_in, const int* in_sizes, int n_in,
                              void* d_out, int out_size)
{
    const float* inp      = (const float*)d_in[0];
    const float* W_rec    = (const float*)d_in[1];
    const float* mem_pot  = (const float*)d_in[2];
    const float* mem_cur  = (const float*)d_in[3];
    const float* mpp      = (const float*)d_in[4];
    const float* mcp      = (const float*)d_in[5];
    const float* st       = (const float*)d_in[6];
    const int*   refrac   = (const int*)d_in[7];
    float* out = (float*)d_out;
    float* Wout = out + OUT_W;

    const int smem_bytes = (2 * TILE_F + 128 + 1024) * 4;   // ~137 KB
    cudaFuncSetAttribute(k_fused, cudaFuncAttributeMaxDynamicSharedMemorySize,
                         smem_bytes);

    k_prologue<<<4 * Nsz / 128, 128>>>(mem_pot, mpp, st);
    k_fused<<<dim3(JBLK, IBLK), 512, smem_bytes>>>(W_rec, Wout);
    k_epilogue<<<BN / 256, 256>>>(inp, mem_pot, mem_cur, mpp, mcp, refrac, out);
}

// round 10
// speedup vs baseline: 1.5456x; 1.5456x over previous
#include <cuda_runtime.h>

// ---------------------------------------------------------------------------
// PCritical step, B=32, N=4096 — fused single pass over W (R4 core, float4
// phase A), sparse-spike GEMMs via ffs loops, separate vectorized epilogue.
// Outputs concatenated float32 in reference return order:
//   S (B,N) | mem_pot_n (B,N) | W_new (N,N) | mem_cur_n (B,N) |
//   mem_pot_p_n (B,N) | mem_cur_p_n (B,N) | refrac_new (B,N)
// ---------------------------------------------------------------------------

#define Bsz 32
#define Nsz 4096
#define BN  (Bsz * Nsz)        // 131072
#define NN  (Nsz * Nsz)        // 16777216

#define C_ALPHA 0.025f
#define C_BETA  0.00025f
#define C_TNOW  10.0f
#define C_INV_TAU_V 0.9801986733067553f
#define C_INV_TAU_I 0.36787944117144233f

#define OUT_S    ((long long)0)
#define OUT_POT  ((long long)BN)
#define OUT_W    ((long long)(2LL * BN))
#define OUT_CUR  ((long long)(2LL * BN + NN))
#define OUT_POTP ((long long)(3LL * BN + NN))
#define OUT_CURP ((long long)(4LL * BN + NN))
#define OUT_REFR ((long long)(5LL * BN + NN))

#define ICHUNKS 16             // 4096 / 256  (grid.y)
#define JCHUNKS 32             // 4096 / 128  (grid.x)
#define PITCH   129            // 129 ≡ 1 (mod 32): rows AND cols conflict-free

// scratch (no dynamic allocation allowed)
__device__ __align__(16) unsigned g_masks[Nsz];          // bit b <=> S[b,n]==1
__device__ __align__(16) float    g_e[Nsz];
__device__ __align__(16) float    g_ie[Nsz];
__device__ __align__(16) float    g_A[Nsz];              // sp ? ALPHA*e  : 0
__device__ __align__(16) float    g_Ai[Nsz];             // sp ? ALPHA*ie : 0
__device__ __align__(16) float    g_accP[ICHUNKS * BN];  // partials S@W_new
__device__ __align__(16) float    g_accTP[JCHUNKS * BN]; // partials S@W_new^T

// ---------------------------------------------------------------------------
// K1: per-neuron batch reductions + exp precompute (4-way batch split).
// ---------------------------------------------------------------------------
__global__ void __launch_bounds__(128) k_prologue(
    const float* __restrict__ mem_pot,
    const float* __restrict__ mem_pot_paired,
    const float* __restrict__ st)
{
    int gid = blockIdx.x * 128 + threadIdx.x;   // 4*Nsz threads
    int n = gid >> 2;
    int q = gid & 3;
    int b0 = q * 8;

    unsigned mp_ = 0u;
    bool anyp = false;
#pragma unroll
    for (int k = 0; k < 8; ++k) {
        int b = b0 + k;
        float mp = mem_pot[b * Nsz + n];
        if (mp > 1.0f) mp_ |= (1u << b);
        float mpp = mem_pot_paired[b * Nsz + n];
        if (((mpp - 1.0f) - C_ALPHA) > 0.0f) anyp = true;
    }
    mp_ |= __shfl_xor_sync(0xffffffffu, mp_, 1);
    anyp = anyp | (bool)__shfl_xor_sync(0xffffffffu, (int)anyp, 1);
    mp_ |= __shfl_xor_sync(0xffffffffu, mp_, 2);
    anyp = anyp | (bool)__shfl_xor_sync(0xffffffffu, (int)anyp, 2);

    if (q == 0) {
        unsigned m = mp_;
        float stn = st[n];
        float maxst = (m == 0xffffffffu) ? C_TNOW
                    : (m ? fmaxf(C_TNOW, stn) : stn);
        float e  = expf(maxst * (1.0f / 50.0f));
        float ie = expf(-maxst * (1.0f / 50.0f));
        g_masks[n] = m;
        g_e[n]  = e;
        g_ie[n] = ie;
        g_A[n]  = anyp ? C_ALPHA * e  : 0.0f;
        g_Ai[n] = anyp ? C_ALPHA * ie : 0.0f;
    }
}

__device__ __forceinline__ float upd1(float w, float A, float Ai, float e, float ie)
{
    float sub = fmaxf(A * ie, Ai * e);        // 0 when row not paired-spiking
    float u = (w + C_BETA) - sub;
    u = fminf(fmaxf(u, 0.0f), 1.0f);
    return (w > 0.0f) ? u : w;                // sign_mask = W_rec > 0
}

// ---------------------------------------------------------------------------
// K2 (fused): W update + both binary-S GEMMs. R4 proven core; phase A uses
// float4 global traffic (1 LDG.128 + 1 STG.128 per row-thread).
// 512 threads, 2 blocks/SM. Tile 256 i x 128 j as 2 subtiles of 128x128.
// ---------------------------------------------------------------------------
__global__ void __launch_bounds__(512, 2) k_fused(
    const float* __restrict__ W, float* __restrict__ Wout)
{
    extern __shared__ float sm[];
    float*    c   = sm;                                  // [128][129]
    unsigned* rbi = (unsigned*)(sm + 128 * PITCH);       // [32][4] rows per b
    unsigned* rbj = rbi + 128;                           // [32][4] cols per b

    const int jc   = blockIdx.x;       // 0..31
    const int ic   = blockIdx.y;       // 0..15
    const int tid  = threadIdx.x;
    const int warp = tid >> 5;         // 0..15
    const int lane = tid & 31;
    const int jg0  = jc * 128;
    const int j4   = lane * 4;

    // per-column exp factors: float4 per lane (phase A)
    float4 e4  = *(const float4*)(g_e  + jg0 + j4);
    float4 ie4 = *(const float4*)(g_ie + jg0 + j4);

    // transposed column masks (block-constant)
    if (warp < 4) {
        unsigned mw = g_masks[jg0 + warp * 32 + lane];
#pragma unroll
        for (int b = 0; b < 32; ++b) {
            unsigned w = __ballot_sync(0xffffffffu, (mw >> b) & 1u);
            if (lane == b) rbj[b * 4 + warp] = w;
        }
    }

    // Phase-B accumulators persist across both subtiles (same ic chunk)
    float aJ0 = 0, aJ1 = 0, aJ2 = 0, aJ3 = 0;   // b = warp
    float bJ0 = 0, bJ1 = 0, bJ2 = 0, bJ3 = 0;   // b = warp + 16

    const int lp = lane * PITCH;

#pragma unroll
    for (int s = 0; s < 2; ++s) {
        const int ig0 = ic * 256 + s * 128;
        if (s) __syncthreads();        // previous subtile fully consumed

        // ---- Phase A: update 8 contiguous rows per warp (float4) ----
#pragma unroll
        for (int r = 0; r < 8; ++r) {
            int il = warp * 8 + r;
            int ig = ig0 + il;
            float A  = g_A[ig];
            float Ai = g_Ai[ig];
            float4 w4 = *(const float4*)(W + (size_t)ig * Nsz + jg0 + j4);
            float4 u;
            u.x = upd1(w4.x, A, Ai, e4.x, ie4.x);
            u.y = upd1(w4.y, A, Ai, e4.y, ie4.y);
            u.z = upd1(w4.z, A, Ai, e4.z, ie4.z);
            u.w = upd1(w4.w, A, Ai, e4.w, ie4.w);
            *(float4*)(Wout + (size_t)ig * Nsz + jg0 + j4) = u;
            float* cr = c + il * PITCH + j4;
            cr[0] = u.x; cr[1] = u.y; cr[2] = u.z; cr[3] = u.w;
        }
        // transposed row masks for this subtile (warps 4..7)
        if (warp >= 4 && warp < 8) {
            int q = warp - 4;
            unsigned mw = g_masks[ig0 + q * 32 + lane];
#pragma unroll
            for (int b = 0; b < 32; ++b) {
                unsigned w = __ballot_sync(0xffffffffu, (mw >> b) & 1u);
                if (lane == b) rbi[b * 4 + q] = w;
            }
        }
        __syncthreads();

        // ---- Phase B: acc[b][j] over active rows (uniform ffs loop) ----
#pragma unroll
        for (int q = 0; q < 4; ++q) {
            unsigned m = rbi[warp * 4 + q];
            while (m) {
                int r = q * 32 + __ffs(m) - 1; m &= m - 1;
                const float* cr = c + r * PITCH;
                aJ0 += cr[lane];
                aJ1 += cr[lane + 32];
                aJ2 += cr[lane + 64];
                aJ3 += cr[lane + 96];
            }
        }
#pragma unroll
        for (int q = 0; q < 4; ++q) {
            unsigned m = rbi[(warp + 16) * 4 + q];
            while (m) {
                int r = q * 32 + __ffs(m) - 1; m &= m - 1;
                const float* cr = c + r * PITCH;
                bJ0 += cr[lane];
                bJ1 += cr[lane + 32];
                bJ2 += cr[lane + 64];
                bJ3 += cr[lane + 96];
            }
        }

        // ---- Phase C: accT[b][i] over active cols ----
        {
            float aI0 = 0, aI1 = 0, aI2 = 0, aI3 = 0;
            float bI0 = 0, bI1 = 0, bI2 = 0, bI3 = 0;
#pragma unroll
            for (int q = 0; q < 4; ++q) {
                unsigned m = rbj[warp * 4 + q];
                while (m) {
                    int j = q * 32 + __ffs(m) - 1; m &= m - 1;
                    const float* cc = c + j + lp;
                    aI0 += cc[0];
                    aI1 += cc[32 * PITCH];
                    aI2 += cc[64 * PITCH];
                    aI3 += cc[96 * PITCH];
                }
            }
#pragma unroll
            for (int q = 0; q < 4; ++q) {
                unsigned m = rbj[(warp + 16) * 4 + q];
                while (m) {
                    int j = q * 32 + __ffs(m) - 1; m &= m - 1;
                    const float* cc = c + j + lp;
                    bI0 += cc[0];
                    bI1 += cc[32 * PITCH];
                    bI2 += cc[64 * PITCH];
                    bI3 += cc[96 * PITCH];
                }
            }
            size_t oa = ((size_t)jc * Bsz + warp) * Nsz + ig0 + lane;
            g_accTP[oa]      = aI0;
            g_accTP[oa + 32] = aI1;
            g_accTP[oa + 64] = aI2;
            g_accTP[oa + 96] = aI3;
            size_t ob = ((size_t)jc * Bsz + warp + 16) * Nsz + ig0 + lane;
            g_accTP[ob]      = bI0;
            g_accTP[ob + 32] = bI1;
            g_accTP[ob + 64] = bI2;
            g_accTP[ob + 96] = bI3;
        }
    }

    // Phase-B partial writes (one per ic chunk)
    {
        size_t oa = ((size_t)ic * Bsz + warp) * Nsz + jg0 + lane;
        g_accP[oa]      = aJ0;
        g_accP[oa + 32] = aJ1;
        g_accP[oa + 64] = aJ2;
        g_accP[oa + 96] = aJ3;
        size_t ob = ((size_t)ic * Bsz + warp + 16) * Nsz + jg0 + lane;
        g_accP[ob]      = bJ0;
        g_accP[ob + 32] = bJ1;
        g_accP[ob + 64] = bJ2;
        g_accP[ob + 96] = bJ3;
    }
}

// ---------------------------------------------------------------------------
// K3: epilogue — reduce partials, integrate, leak, reset, refractory (float4)
// ---------------------------------------------------------------------------
__global__ void __launch_bounds__(256) k_epilogue(
    const float* __restrict__ inp,
    const float* __restrict__ mem_pot,
    const float* __restrict__ mem_cur,
    const float* __restrict__ mem_pot_paired,
    const float* __restrict__ mem_cur_paired,
    const int*   __restrict__ refrac,
    float* __restrict__ out)
{
    int t4 = (blockIdx.x * 256 + threadIdx.x) * 4;   // BN/4 threads
    int b  = t4 >> 12;
    int n  = t4 & (Nsz - 1);

    float4 acc = make_float4(0.f, 0.f, 0.f, 0.f);
#pragma unroll
    for (int cN = 0; cN < ICHUNKS; ++cN) {
        float4 p = *(const float4*)(g_accP + (size_t)cN * BN + t4);
        acc.x += p.x; acc.y += p.y; acc.z += p.z; acc.w += p.w;
    }
    float4 accT = make_float4(0.f, 0.f, 0.f, 0.f);
#pragma unroll
    for (int cN = 0; cN < JCHUNKS; ++cN) {
        float4 p = *(const float4*)(g_accTP + (size_t)cN * BN + t4);
        accT.x += p.x; accT.y += p.y; accT.z += p.z; accT.w += p.w;
    }

    int4   r4   = *(const int4*)(refrac + t4);
    uint4  m4   = *(const uint4*)(g_masks + n);
    float4 mpp4 = *(const float4*)(mem_pot_paired + t4);
    float4 mp4  = *(const float4*)(mem_pot + t4);
    float4 mc4  = *(const float4*)(mem_cur + t4);
    float4 mcp4 = *(const float4*)(mem_cur_paired + t4);
    float4 in4  = *(const float4*)(inp + t4);

    float4 oS, oPot, oCur, oPotP, oCurP, oRef;

    const int   rr[4]   = { r4.x, r4.y, r4.z, r4.w };
    const unsigned mm[4]= { m4.x, m4.y, m4.z, m4.w };
    const float mppA[4] = { mpp4.x, mpp4.y, mpp4.z, mpp4.w };
    const float mpA[4]  = { mp4.x, mp4.y, mp4.z, mp4.w };
    const float mcA[4]  = { mc4.x, mc4.y, mc4.z, mc4.w };
    const float mcpA[4] = { mcp4.x, mcp4.y, mcp4.z, mcp4.w };
    const float inA[4]  = { in4.x, in4.y, in4.z, in4.w };
    const float accA[4] = { acc.x, acc.y, acc.z, acc.w };
    const float accTA[4]= { accT.x, accT.y, accT.z, accT.w };
    float oSA[4], oPotA[4], oCurA[4], oPotPA[4], oCurPA[4], oRefA[4];

#pragma unroll
    for (int k = 0; k < 4; ++k) {
        int r  = rr[k];
        int rd = (r > 0) ? (r - 1) : r;
        bool active = (rd == 0);
        bool s  = ((mm[k] >> b) & 1u) != 0u;
        float mppv = mppA[k];
        bool sp = ((mppv - 1.0f) - C_ALPHA) > 0.0f;

        float mcn  = active ? (inA[k] + accA[k]) + mcA[k] : mcA[k];
        float mcpn = active ? accTA[k] + mcpA[k] : mcpA[k];
        float mpn  = active ? mcn + mpA[k] : mpA[k];
        float mppn = active ? mcpn + mppv : mppv;

        mpn  *= C_INV_TAU_V;
        mcn  *= C_INV_TAU_I;
        mppn *= C_INV_TAU_V;
        mcpn *= C_INV_TAU_I;

        if (s)  mpn  = 0.0f;
        if (sp) mppn = 0.0f;

        oSA[k]    = s ? 1.0f : 0.0f;
        oPotA[k]  = mpn;
        oCurA[k]  = mcn;
        oPotPA[k] = mppn;
        oCurPA[k] = mcpn;
        oRefA[k]  = s ? 2.0f : (float)rd;
    }
    oS    = make_float4(oSA[0], oSA[1], oSA[2], oSA[3]);
    oPot  = make_float4(oPotA[0], oPotA[1], oPotA[2], oPotA[3]);
    oCur  = make_float4(oCurA[0], oCurA[1], oCurA[2], oCurA[3]);
    oPotP = make_float4(oPotPA[0], oPotPA[1], oPotPA[2], oPotPA[3]);
    oCurP = make_float4(oCurPA[0], oCurPA[1], oCurPA[2], oCurPA[3]);
    oRef  = make_float4(oRefA[0], oRefA[1], oRefA[2], oRefA[3]);

    *(float4*)(out + OUT_S    + t4) = oS;
    *(float4*)(out + OUT_POT  + t4) = oPot;
    *(float4*)(out + OUT_CUR  + t4) = oCur;
    *(float4*)(out + OUT_POTP + t4) = oPotP;
    *(float4*)(out + OUT_CURP + t4) = oCurP;
    *(float4*)(out + OUT_REFR + t4) = oRef;
}

// ---------------------------------------------------------------------------
extern "C" void kernel_launch(void* const* d_in, const int* in_sizes, int n_in,
                              void* d_out, int out_size)
{
    const float* inp      = (const float*)d_in[0];
    const float* W_rec    = (const float*)d_in[1];
    const float* mem_pot  = (const float*)d_in[2];
    const float* mem_cur  = (const float*)d_in[3];
    const float* mpp      = (const float*)d_in[4];
    const float* mcp      = (const float*)d_in[5];
    const float* st       = (const float*)d_in[6];
    const int*   refrac   = (const int*)d_in[7];
    float* out = (float*)d_out;
    float* Wout = out + OUT_W;

    const int smem_bytes = (128 * PITCH + 256) * 4;   // ~67 KB -> 2 blocks/SM
    cudaFuncSetAttribute(k_fused, cudaFuncAttributeMaxDynamicSharedMemorySize,
                         smem_bytes);

    k_prologue<<<4 * Nsz / 128, 128>>>(mem_pot, mpp, st);
    k_fused<<<dim3(JCHUNKS, ICHUNKS), 512, smem_bytes>>>(W_rec, Wout);
    k_epilogue<<<BN / 4 / 256, 256>>>(inp, mem_pot, mem_cur, mpp, mcp, refrac, out);
}

// round 11
// speedup vs baseline: 1.5509x; 1.0034x over previous
#include <cuda_runtime.h>

// ---------------------------------------------------------------------------
// PCritical step, B=32, N=4096 — fused single pass over W (R4 proven core),
// coalesced prologue, vectorized epilogue.
// Outputs concatenated float32 in reference return order:
//   S (B,N) | mem_pot_n (B,N) | W_new (N,N) | mem_cur_n (B,N) |
//   mem_pot_p_n (B,N) | mem_cur_p_n (B,N) | refrac_new (B,N)
// ---------------------------------------------------------------------------

#define Bsz 32
#define Nsz 4096
#define BN  (Bsz * Nsz)        // 131072
#define NN  (Nsz * Nsz)        // 16777216

#define C_ALPHA 0.025f
#define C_BETA  0.00025f
#define C_TNOW  10.0f
#define C_INV_TAU_V 0.9801986733067553f
#define C_INV_TAU_I 0.36787944117144233f

#define OUT_S    ((long long)0)
#define OUT_POT  ((long long)BN)
#define OUT_W    ((long long)(2LL * BN))
#define OUT_CUR  ((long long)(2LL * BN + NN))
#define OUT_POTP ((long long)(3LL * BN + NN))
#define OUT_CURP ((long long)(4LL * BN + NN))
#define OUT_REFR ((long long)(5LL * BN + NN))

#define ICHUNKS 16             // 4096 / 256  (grid.y)
#define JCHUNKS 32             // 4096 / 128  (grid.x)
#define PITCH   129            // 129 ≡ 1 (mod 32): rows AND cols conflict-free

// scratch (no dynamic allocation allowed)
__device__ __align__(16) unsigned g_masks[Nsz];          // bit b <=> S[b,n]==1
__device__ __align__(16) float    g_e[Nsz];
__device__ __align__(16) float    g_ie[Nsz];
__device__ __align__(16) float    g_A[Nsz];              // sp ? ALPHA*e  : 0
__device__ __align__(16) float    g_Ai[Nsz];             // sp ? ALPHA*ie : 0
__device__ __align__(16) float    g_accP[ICHUNKS * BN];  // partials S@W_new
__device__ __align__(16) float    g_accTP[JCHUNKS * BN]; // partials S@W_new^T

// ---------------------------------------------------------------------------
// K1: per-neuron batch reductions + exp precompute, fully coalesced.
// Block = 128 threads = 4 warps; warp w owns batches [8w, 8w+8); lanes own 32
// consecutive neurons -> every LDG covers a full 128B line. Cross-warp OR via
// smem, 32 threads finalize.
// ---------------------------------------------------------------------------
__global__ void __launch_bounds__(128) k_prologue(
    const float* __restrict__ mem_pot,
    const float* __restrict__ mem_pot_paired,
    const float* __restrict__ st)
{
    __shared__ unsigned spm[4][32];
    __shared__ unsigned ppm[4][32];

    const int warp = threadIdx.x >> 5;
    const int lane = threadIdx.x & 31;
    const int n = blockIdx.x * 32 + lane;

    unsigned m = 0u, p = 0u;
#pragma unroll
    for (int k = 0; k < 8; ++k) {
        int b = warp * 8 + k;
        float mp = mem_pot[b * Nsz + n];
        if (mp > 1.0f) m |= (1u << b);
        float mpp = mem_pot_paired[b * Nsz + n];
        if (((mpp - 1.0f) - C_ALPHA) > 0.0f) p = 1u;
    }
    spm[warp][lane] = m;
    ppm[warp][lane] = p;
    __syncthreads();

    if (threadIdx.x < 32) {
        unsigned mm = spm[0][lane] | spm[1][lane] | spm[2][lane] | spm[3][lane];
        bool anyp = (ppm[0][lane] | ppm[1][lane] | ppm[2][lane] | ppm[3][lane]) != 0u;
        float stn = st[n];
        float maxst = (mm == 0xffffffffu) ? C_TNOW
                    : (mm ? fmaxf(C_TNOW, stn) : stn);
        float e  = expf(maxst * (1.0f / 50.0f));
        float ie = expf(-maxst * (1.0f / 50.0f));
        g_masks[n] = mm;
        g_e[n]  = e;
        g_ie[n] = ie;
        g_A[n]  = anyp ? C_ALPHA * e  : 0.0f;
        g_Ai[n] = anyp ? C_ALPHA * ie : 0.0f;
    }
}

__device__ __forceinline__ float upd1(float w, float A, float Ai, float e, float ie)
{
    float sub = fmaxf(A * ie, Ai * e);        // 0 when row not paired-spiking
    float u = (w + C_BETA) - sub;
    u = fminf(fmaxf(u, 0.0f), 1.0f);
    return (w > 0.0f) ? u : w;                // sign_mask = W_rec > 0
}

// ---------------------------------------------------------------------------
// K2 (fused): W update + both binary-S GEMMs; spike-sparse ffs loops.
// R4 proven core: 512 threads, 2 blocks/SM, tile 256 i x 128 j as 2 subtiles.
// Scalar lane-stride-1 global & smem accesses (conflict-free STS; pitch 129
// gives conflict-free row AND column LDS).
// ---------------------------------------------------------------------------
__global__ void __launch_bounds__(512, 2) k_fused(
    const float* __restrict__ W, float* __restrict__ Wout)
{
    extern __shared__ float sm[];
    float*    c   = sm;                                  // [128][129]
    unsigned* rbi = (unsigned*)(sm + 128 * PITCH);       // [32][4] rows per b
    unsigned* rbj = rbi + 128;                           // [32][4] cols per b

    const int jc   = blockIdx.x;       // 0..31
    const int ic   = blockIdx.y;       // 0..15
    const int tid  = threadIdx.x;
    const int warp = tid >> 5;         // 0..15
    const int lane = tid & 31;
    const int jg0  = jc * 128;

    // per-column exp factors (block-constant)
    float e0  = g_e[jg0 + lane];       float ie0 = g_ie[jg0 + lane];
    float e1  = g_e[jg0 + lane + 32];  float ie1 = g_ie[jg0 + lane + 32];
    float e2  = g_e[jg0 + lane + 64];  float ie2 = g_ie[jg0 + lane + 64];
    float e3  = g_e[jg0 + lane + 96];  float ie3 = g_ie[jg0 + lane + 96];

    // transposed column masks (block-constant)
    if (warp < 4) {
        unsigned mw = g_masks[jg0 + warp * 32 + lane];
#pragma unroll
        for (int b = 0; b < 32; ++b) {
            unsigned w = __ballot_sync(0xffffffffu, (mw >> b) & 1u);
            if (lane == b) rbj[b * 4 + warp] = w;
        }
    }

    // Phase-B accumulators persist across both subtiles (same ic chunk)
    float aJ0 = 0, aJ1 = 0, aJ2 = 0, aJ3 = 0;   // b = warp
    float bJ0 = 0, bJ1 = 0, bJ2 = 0, bJ3 = 0;   // b = warp + 16

    const int lp = lane * PITCH;

#pragma unroll
    for (int s = 0; s < 2; ++s) {
        const int ig0 = ic * 256 + s * 128;
        if (s) __syncthreads();        // previous subtile fully consumed

        // ---- Phase A: update 8 contiguous rows per warp ----
#pragma unroll
        for (int r = 0; r < 8; ++r) {
            int il = warp * 8 + r;
            int ig = ig0 + il;
            float A  = g_A[ig];
            float Ai = g_Ai[ig];
            const float* wr = W    + (size_t)ig * Nsz + jg0;
            float*       wo = Wout + (size_t)ig * Nsz + jg0;
            float w0 = wr[lane];
            float w1 = wr[lane + 32];
            float w2 = wr[lane + 64];
            float w3 = wr[lane + 96];
            float u0 = upd1(w0, A, Ai, e0, ie0);
            float u1 = upd1(w1, A, Ai, e1, ie1);
            float u2 = upd1(w2, A, Ai, e2, ie2);
            float u3 = upd1(w3, A, Ai, e3, ie3);
            wo[lane]      = u0;
            wo[lane + 32] = u1;
            wo[lane + 64] = u2;
            wo[lane + 96] = u3;
            float* cr = c + il * PITCH;
            cr[lane]      = u0;
            cr[lane + 32] = u1;
            cr[lane + 64] = u2;
            cr[lane + 96] = u3;
        }
        // transposed row masks for this subtile (warps 4..7)
        if (warp >= 4 && warp < 8) {
            int q = warp - 4;
            unsigned mw = g_masks[ig0 + q * 32 + lane];
#pragma unroll
            for (int b = 0; b < 32; ++b) {
                unsigned w = __ballot_sync(0xffffffffu, (mw >> b) & 1u);
                if (lane == b) rbi[b * 4 + q] = w;
            }
        }
        __syncthreads();

        // ---- Phase B: acc[b][j] over active rows (uniform ffs loop) ----
#pragma unroll
        for (int q = 0; q < 4; ++q) {
            unsigned m = rbi[warp * 4 + q];
            while (m) {
                int r = q * 32 + __ffs(m) - 1; m &= m - 1;
                const float* cr = c + r * PITCH;
                aJ0 += cr[lane];
                aJ1 += cr[lane + 32];
                aJ2 += cr[lane + 64];
                aJ3 += cr[lane + 96];
            }
        }
#pragma unroll
        for (int q = 0; q < 4; ++q) {
            unsigned m = rbi[(warp + 16) * 4 + q];
            while (m) {
                int r = q * 32 + __ffs(m) - 1; m &= m - 1;
                const float* cr = c + r * PITCH;
                bJ0 += cr[lane];
                bJ1 += cr[lane + 32];
                bJ2 += cr[lane + 64];
                bJ3 += cr[lane + 96];
            }
        }

        // ---- Phase C: accT[b][i] over active cols ----
        {
            float aI0 = 0, aI1 = 0, aI2 = 0, aI3 = 0;
            float bI0 = 0, bI1 = 0, bI2 = 0, bI3 = 0;
#pragma unroll
            for (int q = 0; q < 4; ++q) {
                unsigned m = rbj[warp * 4 + q];
                while (m) {
                    int j = q * 32 + __ffs(m) - 1; m &= m - 1;
                    const float* cc = c + j + lp;
                    aI0 += cc[0];
                    aI1 += cc[32 * PITCH];
                    aI2 += cc[64 * PITCH];
                    aI3 += cc[96 * PITCH];
                }
            }
#pragma unroll
            for (int q = 0; q < 4; ++q) {
                unsigned m = rbj[(warp + 16) * 4 + q];
                while (m) {
                    int j = q * 32 + __ffs(m) - 1; m &= m - 1;
                    const float* cc = c + j + lp;
                    bI0 += cc[0];
                    bI1 += cc[32 * PITCH];
                    bI2 += cc[64 * PITCH];
                    bI3 += cc[96 * PITCH];
                }
            }
            size_t oa = ((size_t)jc * Bsz + warp) * Nsz + ig0 + lane;
            g_accTP[oa]      = aI0;
            g_accTP[oa + 32] = aI1;
            g_accTP[oa + 64] = aI2;
            g_accTP[oa + 96] = aI3;
            size_t ob = ((size_t)jc * Bsz + warp + 16) * Nsz + ig0 + lane;
            g_accTP[ob]      = bI0;
            g_accTP[ob + 32] = bI1;
            g_accTP[ob + 64] = bI2;
            g_accTP[ob + 96] = bI3;
        }
    }

    // Phase-B partial writes (one per ic chunk)
    {
        size_t oa = ((size_t)ic * Bsz + warp) * Nsz + jg0 + lane;
        g_accP[oa]      = aJ0;
        g_accP[oa + 32] = aJ1;
        g_accP[oa + 64] = aJ2;
        g_accP[oa + 96] = aJ3;
        size_t ob = ((size_t)ic * Bsz + warp + 16) * Nsz + jg0 + lane;
        g_accP[ob]      = bJ0;
        g_accP[ob + 32] = bJ1;
        g_accP[ob + 64] = bJ2;
        g_accP[ob + 96] = bJ3;
    }
}

// ---------------------------------------------------------------------------
// K3: epilogue — reduce partials, integrate, leak, reset, refractory (float4)
// ---------------------------------------------------------------------------
__global__ void __launch_bounds__(256) k_epilogue(
    const float* __restrict__ inp,
    const float* __restrict__ mem_pot,
    const float* __restrict__ mem_cur,
    const float* __restrict__ mem_pot_paired,
    const float* __restrict__ mem_cur_paired,
    const int*   __restrict__ refrac,
    float* __restrict__ out)
{
    int t4 = (blockIdx.x * 256 + threadIdx.x) * 4;   // BN/4 threads
    int b  = t4 >> 12;
    int n  = t4 & (Nsz - 1);

    float4 acc = make_float4(0.f, 0.f, 0.f, 0.f);
#pragma unroll
    for (int cN = 0; cN < ICHUNKS; ++cN) {
        float4 p = *(const float4*)(g_accP + (size_t)cN * BN + t4);
        acc.x += p.x; acc.y += p.y; acc.z += p.z; acc.w += p.w;
    }
    float4 accT = make_float4(0.f, 0.f, 0.f, 0.f);
#pragma unroll
    for (int cN = 0; cN < JCHUNKS; ++cN) {
        float4 p = *(const float4*)(g_accTP + (size_t)cN * BN + t4);
        accT.x += p.x; accT.y += p.y; accT.z += p.z; accT.w += p.w;
    }

    int4   r4   = *(const int4*)(refrac + t4);
    uint4  m4   = *(const uint4*)(g_masks + n);
    float4 mpp4 = *(const float4*)(mem_pot_paired + t4);
    float4 mp4  = *(const float4*)(mem_pot + t4);
    float4 mc4  = *(const float4*)(mem_cur + t4);
    float4 mcp4 = *(const float4*)(mem_cur_paired + t4);
    float4 in4  = *(const float4*)(inp + t4);

    const int      rr[4]   = { r4.x, r4.y, r4.z, r4.w };
    const unsigned mm[4]   = { m4.x, m4.y, m4.z, m4.w };
    const float    mppA[4] = { mpp4.x, mpp4.y, mpp4.z, mpp4.w };
    const float    mpA[4]  = { mp4.x, mp4.y, mp4.z, mp4.w };
    const float    mcA[4]  = { mc4.x, mc4.y, mc4.z, mc4.w };
    const float    mcpA[4] = { mcp4.x, mcp4.y, mcp4.z, mcp4.w };
    const float    inA[4]  = { in4.x, in4.y, in4.z, in4.w };
    const float    accA[4] = { acc.x, acc.y, acc.z, acc.w };
    const float    accTA[4]= { accT.x, accT.y, accT.z, accT.w };
    float oSA[4], oPotA[4], oCurA[4], oPotPA[4], oCurPA[4], oRefA[4];

#pragma unroll
    for (int k = 0; k < 4; ++k) {
        int r  = rr[k];
        int rd = (r > 0) ? (r - 1) : r;
        bool active = (rd == 0);
        bool s  = ((mm[k] >> b) & 1u) != 0u;
        float mppv = mppA[k];
        bool sp = ((mppv - 1.0f) - C_ALPHA) > 0.0f;

        float mcn  = active ? (inA[k] + accA[k]) + mcA[k] : mcA[k];
        float mcpn = active ? accTA[k] + mcpA[k] : mcpA[k];
        float mpn  = active ? mcn + mpA[k] : mpA[k];
        float mppn = active ? mcpn + mppv : mppv;

        mpn  *= C_INV_TAU_V;
        mcn  *= C_INV_TAU_I;
        mppn *= C_INV_TAU_V;
        mcpn *= C_INV_TAU_I;

        if (s)  mpn  = 0.0f;
        if (sp) mppn = 0.0f;

        oSA[k]    = s ? 1.0f : 0.0f;
        oPotA[k]  = mpn;
        oCurA[k]  = mcn;
        oPotPA[k] = mppn;
        oCurPA[k] = mcpn;
        oRefA[k]  = s ? 2.0f : (float)rd;
    }

    *(float4*)(out + OUT_S    + t4) = make_float4(oSA[0], oSA[1], oSA[2], oSA[3]);
    *(float4*)(out + OUT_POT  + t4) = make_float4(oPotA[0], oPotA[1], oPotA[2], oPotA[3]);
    *(float4*)(out + OUT_CUR  + t4) = make_float4(oCurA[0], oCurA[1], oCurA[2], oCurA[3]);
    *(float4*)(out + OUT_POTP + t4) = make_float4(oPotPA[0], oPotPA[1], oPotPA[2], oPotPA[3]);
    *(float4*)(out + OUT_CURP + t4) = make_float4(oCurPA[0], oCurPA[1], oCurPA[2], oCurPA[3]);
    *(float4*)(out + OUT_REFR + t4) = make_float4(oRefA[0], oRefA[1], oRefA[2], oRefA[3]);
}

// ---------------------------------------------------------------------------
extern "C" void kernel_launch(void* const* d_in, const int* in_sizes, int n_in,
                              void* d_out, int out_size)
{
    const float* inp      = (const float*)d_in[0];
    const float* W_rec    = (const float*)d_in[1];
    const float* mem_pot  = (const float*)d_in[2];
    const float* mem_cur  = (const float*)d_in[3];
    const float* mpp      = (const float*)d_in[4];
    const float* mcp      = (const float*)d_in[5];
    const float* st       = (const float*)d_in[6];
    const int*   refrac   = (const int*)d_in[7];
    float* out = (float*)d_out;
    float* Wout = out + OUT_W;

    const int smem_bytes = (128 * PITCH + 256) * 4;   // ~67 KB -> 2 blocks/SM
    cudaFuncSetAttribute(k_fused, cudaFuncAttributeMaxDynamicSharedMemorySize,
                         smem_bytes);

    k_prologue<<<Nsz / 32, 128>>>(mem_pot, mpp, st);
    k_fused<<<dim3(JCHUNKS, ICHUNKS), 512, smem_bytes>>>(W_rec, Wout);
    k_epilogue<<<BN / 4 / 256, 256>>>(inp, mem_pot, mem_cur, mpp, mcp, refrac, out);
}

// round 12
// speedup vs baseline: 1.6045x; 1.0346x over previous
#include <cuda_runtime.h>

// ---------------------------------------------------------------------------
// PCritical step, B=32, N=4096 — fused single pass over W (R4 proven subtile
// core, 256x256 block tile, smem-accumulated accT partials).
// Outputs concatenated float32 in reference return order:
//   S (B,N) | mem_pot_n (B,N) | W_new (N,N) | mem_cur_n (B,N) |
//   mem_pot_p_n (B,N) | mem_cur_p_n (B,N) | refrac_new (B,N)
// ---------------------------------------------------------------------------

#define Bsz 32
#define Nsz 4096
#define BN  (Bsz * Nsz)        // 131072
#define NN  (Nsz * Nsz)        // 16777216

#define C_ALPHA 0.025f
#define C_BETA  0.00025f
#define C_TNOW  10.0f
#define C_INV_TAU_V 0.9801986733067553f
#define C_INV_TAU_I 0.36787944117144233f

#define OUT_S    ((long long)0)
#define OUT_POT  ((long long)BN)
#define OUT_W    ((long long)(2LL * BN))
#define OUT_CUR  ((long long)(2LL * BN + NN))
#define OUT_POTP ((long long)(3LL * BN + NN))
#define OUT_CURP ((long long)(4LL * BN + NN))
#define OUT_REFR ((long long)(5LL * BN + NN))

#define ICH   16               // 4096 / 256 row chunks   (grid.y)
#define JCH   16               // 4096 / 256 col chunks   (grid.x)
#define PITCH 129              // 129 ≡ 1 (mod 32): rows AND cols conflict-free

// scratch (no dynamic allocation allowed)
__device__ __align__(16) unsigned g_masks[Nsz];       // bit b <=> S[b,n]==1
__device__ __align__(16) float    g_e[Nsz];
__device__ __align__(16) float    g_ie[Nsz];
__device__ __align__(16) float    g_A[Nsz];           // sp ? ALPHA*e  : 0
__device__ __align__(16) float    g_Ai[Nsz];          // sp ? ALPHA*ie : 0
__device__ __align__(16) float    g_accP[ICH * BN];   // partials S@W_new
__device__ __align__(16) float    g_accTP[JCH * BN];  // partials S@W_new^T

// ---------------------------------------------------------------------------
// K1: per-neuron batch reductions + exp precompute, coalesced.
// ---------------------------------------------------------------------------
__global__ void __launch_bounds__(128) k_prologue(
    const float* __restrict__ mem_pot,
    const float* __restrict__ mem_pot_paired,
    const float* __restrict__ st)
{
    __shared__ unsigned spm[4][32];
    __shared__ unsigned ppm[4][32];

    const int warp = threadIdx.x >> 5;
    const int lane = threadIdx.x & 31;
    const int n = blockIdx.x * 32 + lane;

    unsigned m = 0u, p = 0u;
#pragma unroll
    for (int k = 0; k < 8; ++k) {
        int b = warp * 8 + k;
        float mp = mem_pot[b * Nsz + n];
        if (mp > 1.0f) m |= (1u << b);
        float mpp = mem_pot_paired[b * Nsz + n];
        if (((mpp - 1.0f) - C_ALPHA) > 0.0f) p = 1u;
    }
    spm[warp][lane] = m;
    ppm[warp][lane] = p;
    __syncthreads();

    if (threadIdx.x < 32) {
        unsigned mm = spm[0][lane] | spm[1][lane] | spm[2][lane] | spm[3][lane];
        bool anyp = (ppm[0][lane] | ppm[1][lane] | ppm[2][lane] | ppm[3][lane]) != 0u;
        float stn = st[n];
        float maxst = (mm == 0xffffffffu) ? C_TNOW
                    : (mm ? fmaxf(C_TNOW, stn) : stn);
        float e  = expf(maxst * (1.0f / 50.0f));
        float ie = expf(-maxst * (1.0f / 50.0f));
        g_masks[n] = mm;
        g_e[n]  = e;
        g_ie[n] = ie;
        g_A[n]  = anyp ? C_ALPHA * e  : 0.0f;
        g_Ai[n] = anyp ? C_ALPHA * ie : 0.0f;
    }
}

__device__ __forceinline__ float upd1(float w, float A, float Ai, float e, float ie)
{
    float sub = fmaxf(A * ie, Ai * e);        // 0 when row not paired-spiking
    float u = (w + C_BETA) - sub;
    u = fminf(fmaxf(u, 0.0f), 1.0f);
    return (w > 0.0f) ? u : w;                // sign_mask = W_rec > 0
}

// ---------------------------------------------------------------------------
// K2 (fused): block tile 256 i x 256 j as four 128x128 subtiles, order
// (sj,si) = (0,0),(0,1),(1,0),(1,1). Phase A/B/C per subtile are the proven
// R4 loops. Phase-B accumulators live per j-half (registers); phase-C
// accumulators live in smem across j-halves -> accTP chunks halved to 16.
// 512 threads, 2 blocks/SM, 256 blocks.
// ---------------------------------------------------------------------------
__global__ void __launch_bounds__(512, 2) k_fused(
    const float* __restrict__ W, float* __restrict__ Wout)
{
    extern __shared__ float sm[];
    float*    c    = sm;                                 // [128][129]
    float*    cacc = sm + 128 * PITCH;                   // [32][256] accT acc
    unsigned* rbi  = (unsigned*)(cacc + 32 * 256);       // [32][8] row words
    unsigned* rbj  = rbi + 256;                          // [32][8] col words

    const int jc   = blockIdx.x;       // 0..15
    const int ic   = blockIdx.y;       // 0..15
    const int tid  = threadIdx.x;
    const int warp = tid >> 5;         // 0..15
    const int lane = tid & 31;
    const int jg0  = jc * 256;
    const int igB  = ic * 256;
    const int lp   = lane * PITCH;

    // zero accT smem accumulators
    for (int k = tid; k < 32 * 256; k += 512) cacc[k] = 0.0f;

    // transposed masks for the whole block tile:
    // warps 0-7: row groups (256 rows), warps 8-15: col groups (256 cols)
    {
        int g = warp & 7;
        unsigned mw = (warp < 8) ? g_masks[igB + g * 32 + lane]
                                 : g_masks[jg0 + g * 32 + lane];
        unsigned* dst = (warp < 8) ? rbi : rbj;
#pragma unroll
        for (int b = 0; b < 32; ++b) {
            unsigned w = __ballot_sync(0xffffffffu, (mw >> b) & 1u);
            if (lane == b) dst[b * 8 + g] = w;
        }
    }
    // (first post-phase-A __syncthreads orders these for all readers)

    // Phase-B accumulators for the current j-half
    float aJ0, aJ1, aJ2, aJ3, bJ0, bJ1, bJ2, bJ3;

#pragma unroll
    for (int sj = 0; sj < 2; ++sj) {
        const int jg = jg0 + sj * 128;

        // per-column exp factors for this j-half
        float e0  = g_e[jg + lane];       float ie0 = g_ie[jg + lane];
        float e1  = g_e[jg + lane + 32];  float ie1 = g_ie[jg + lane + 32];
        float e2  = g_e[jg + lane + 64];  float ie2 = g_ie[jg + lane + 64];
        float e3  = g_e[jg + lane + 96];  float ie3 = g_ie[jg + lane + 96];

        aJ0 = aJ1 = aJ2 = aJ3 = 0.0f;
        bJ0 = bJ1 = bJ2 = bJ3 = 0.0f;

#pragma unroll
        for (int si = 0; si < 2; ++si) {
            const int ig0 = igB + si * 128;
            if (sj | si) __syncthreads();   // previous subtile fully consumed

            // ---- Phase A: update 8 contiguous rows per warp ----
#pragma unroll
            for (int r = 0; r < 8; ++r) {
                int il = warp * 8 + r;
                int ig = ig0 + il;
                float A  = g_A[ig];
                float Ai = g_Ai[ig];
                const float* wr = W    + (size_t)ig * Nsz + jg;
                float*       wo = Wout + (size_t)ig * Nsz + jg;
                float w0 = wr[lane];
                float w1 = wr[lane + 32];
                float w2 = wr[lane + 64];
                float w3 = wr[lane + 96];
                float u0 = upd1(w0, A, Ai, e0, ie0);
                float u1 = upd1(w1, A, Ai, e1, ie1);
                float u2 = upd1(w2, A, Ai, e2, ie2);
                float u3 = upd1(w3, A, Ai, e3, ie3);
                wo[lane]      = u0;
                wo[lane + 32] = u1;
                wo[lane + 64] = u2;
                wo[lane + 96] = u3;
                float* cr = c + il * PITCH;
                cr[lane]      = u0;
                cr[lane + 32] = u1;
                cr[lane + 64] = u2;
                cr[lane + 96] = u3;
            }
            __syncthreads();

            // ---- Phase B: acc[b][j] over active rows (uniform ffs loop) ----
#pragma unroll
            for (int q = 0; q < 4; ++q) {
                unsigned m = rbi[warp * 8 + si * 4 + q];
                while (m) {
                    int r = q * 32 + __ffs(m) - 1; m &= m - 1;
                    const float* cr = c + r * PITCH;
                    aJ0 += cr[lane];
                    aJ1 += cr[lane + 32];
                    aJ2 += cr[lane + 64];
                    aJ3 += cr[lane + 96];
                }
            }
#pragma unroll
            for (int q = 0; q < 4; ++q) {
                unsigned m = rbi[(warp + 16) * 8 + si * 4 + q];
                while (m) {
                    int r = q * 32 + __ffs(m) - 1; m &= m - 1;
                    const float* cr = c + r * PITCH;
                    bJ0 += cr[lane];
                    bJ1 += cr[lane + 32];
                    bJ2 += cr[lane + 64];
                    bJ3 += cr[lane + 96];
                }
            }

            // ---- Phase C: accT[b][i] over active cols -> smem accumulator ----
            {
                float aI0 = 0, aI1 = 0, aI2 = 0, aI3 = 0;
                float bI0 = 0, bI1 = 0, bI2 = 0, bI3 = 0;
#pragma unroll
                for (int q = 0; q < 4; ++q) {
                    unsigned m = rbj[warp * 8 + sj * 4 + q];
                    while (m) {
                        int j = q * 32 + __ffs(m) - 1; m &= m - 1;
                        const float* cc = c + j + lp;
                        aI0 += cc[0];
                        aI1 += cc[32 * PITCH];
                        aI2 += cc[64 * PITCH];
                        aI3 += cc[96 * PITCH];
                    }
                }
#pragma unroll
                for (int q = 0; q < 4; ++q) {
                    unsigned m = rbj[(warp + 16) * 8 + sj * 4 + q];
                    while (m) {
                        int j = q * 32 + __ffs(m) - 1; m &= m - 1;
                        const float* cc = c + j + lp;
                        bI0 += cc[0];
                        bI1 += cc[32 * PITCH];
                        bI2 += cc[64 * PITCH];
                        bI3 += cc[96 * PITCH];
                    }
                }
                // fold into smem accT accumulator (warp-private rows, no races)
                float* pa = cacc + warp * 256 + si * 128 + lane;
                pa[0]  += aI0;
                pa[32] += aI1;
                pa[64] += aI2;
                pa[96] += aI3;
                float* pb = cacc + (warp + 16) * 256 + si * 128 + lane;
                pb[0]  += bI0;
                pb[32] += bI1;
                pb[64] += bI2;
                pb[96] += bI3;
            }
        }

        // write Phase-B partials for this j-half (one per ic chunk)
        {
            size_t oa = ((size_t)ic * Bsz + warp) * Nsz + jg + lane;
            g_accP[oa]      = aJ0;
            g_accP[oa + 32] = aJ1;
            g_accP[oa + 64] = aJ2;
            g_accP[oa + 96] = aJ3;
            size_t ob = ((size_t)ic * Bsz + warp + 16) * Nsz + jg + lane;
            g_accP[ob]      = bJ0;
            g_accP[ob + 32] = bJ1;
            g_accP[ob + 64] = bJ2;
            g_accP[ob + 96] = bJ3;
        }
    }

    // dump smem accT accumulator -> g_accTP[jc][b][igB + il]  (coalesced)
    __syncthreads();
#pragma unroll
    for (int k = 0; k < 16; ++k) {
        int idx = tid + 512 * k;          // 0..8191
        int b   = idx >> 8;
        int il  = idx & 255;
        g_accTP[((size_t)jc * Bsz + b) * Nsz + igB + il] = cacc[b * 256 + il];
    }
}

// ---------------------------------------------------------------------------
// K3: epilogue — reduce partials, integrate, leak, reset, refractory
// ---------------------------------------------------------------------------
__global__ void __launch_bounds__(256) k_epilogue(
    const float* __restrict__ inp,
    const float* __restrict__ mem_pot,
    const float* __restrict__ mem_cur,
    const float* __restrict__ mem_pot_paired,
    const float* __restrict__ mem_cur_paired,
    const int*   __restrict__ refrac,
    float* __restrict__ out)
{
    int t = blockIdx.x * 256 + threadIdx.x;   // BN threads
    int b = t >> 12;
    int n = t & (Nsz - 1);

    float acc = 0.0f;
#pragma unroll
    for (int cN = 0; cN < ICH; ++cN) acc += g_accP[(size_t)cN * BN + t];
    float accT = 0.0f;
#pragma unroll
    for (int cN = 0; cN < JCH; ++cN) accT += g_accTP[(size_t)cN * BN + t];

    int r  = refrac[t];
    int rd = (r > 0) ? (r - 1) : r;
    bool active = (rd == 0);

    unsigned m = g_masks[n];
    bool s  = ((m >> b) & 1u) != 0u;
    float mppv = mem_pot_paired[t];
    bool sp = ((mppv - 1.0f) - C_ALPHA) > 0.0f;

    float mp   = mem_pot[t];
    float mc   = mem_cur[t];
    float mcpv = mem_cur_paired[t];

    float mcn  = active ? (inp[t] + acc) + mc : mc;
    float mcpn = active ? accT + mcpv : mcpv;
    float mpn  = active ? mcn + mp : mp;
    float mppn = active ? mcpn + mppv : mppv;

    mpn  *= C_INV_TAU_V;
    mcn  *= C_INV_TAU_I;
    mppn *= C_INV_TAU_V;
    mcpn *= C_INV_TAU_I;

    if (s)  mpn  = 0.0f;
    if (sp) mppn = 0.0f;
    float rn = s ? 2.0f : (float)rd;

    out[OUT_S    + t] = s ? 1.0f : 0.0f;
    out[OUT_POT  + t] = mpn;
    out[OUT_CUR  + t] = mcn;
    out[OUT_POTP + t] = mppn;
    out[OUT_CURP + t] = mcpn;
    out[OUT_REFR + t] = rn;
}

// ---------------------------------------------------------------------------
extern "C" void kernel_launch(void* const* d_in, const int* in_sizes, int n_in,
                              void* d_out, int out_size)
{
    const float* inp      = (const float*)d_in[0];
    const float* W_rec    = (const float*)d_in[1];
    const float* mem_pot  = (const float*)d_in[2];
    const float* mem_cur  = (const float*)d_in[3];
    const float* mpp      = (const float*)d_in[4];
    const float* mcp      = (const float*)d_in[5];
    const float* st       = (const float*)d_in[6];
    const int*   refrac   = (const int*)d_in[7];
    float* out = (float*)d_out;
    float* Wout = out + OUT_W;

    const int smem_bytes = (128 * PITCH + 32 * 256 + 512) * 4;  // ~100.5 KB
    cudaFuncSetAttribute(k_fused, cudaFuncAttributeMaxDynamicSharedMemorySize,
                         smem_bytes);

    k_prologue<<<Nsz / 32, 128>>>(mem_pot, mpp, st);
    k_fused<<<dim3(JCH, ICH), 512, smem_bytes>>>(W_rec, Wout);
    k_epilogue<<<BN / 256, 256>>>(inp, mem_pot, mem_cur, mpp, mcp, refrac, out);
}

// round 13
// speedup vs baseline: 1.6534x; 1.0305x over previous
#include <cuda_runtime.h>

// ---------------------------------------------------------------------------
// PCritical step, B=32, N=4096 — fully fused: per-block neuron precompute
// (phase 0) + single pass over W (256x256 tile, four 128x128 subtiles) +
// smem-accumulated accT partials. Separate epilogue reduces partials.
// Outputs concatenated float32 in reference return order:
//   S (B,N) | mem_pot_n (B,N) | W_new (N,N) | mem_cur_n (B,N) |
//   mem_pot_p_n (B,N) | mem_cur_p_n (B,N) | refrac_new (B,N)
// ---------------------------------------------------------------------------

#define Bsz 32
#define Nsz 4096
#define BN  (Bsz * Nsz)        // 131072
#define NN  (Nsz * Nsz)        // 16777216

#define C_ALPHA 0.025f
#define C_BETA  0.00025f
#define C_TNOW  10.0f
#define C_INV_TAU_V 0.9801986733067553f
#define C_INV_TAU_I 0.36787944117144233f

#define OUT_S    ((long long)0)
#define OUT_POT  ((long long)BN)
#define OUT_W    ((long long)(2LL * BN))
#define OUT_CUR  ((long long)(2LL * BN + NN))
#define OUT_POTP ((long long)(3LL * BN + NN))
#define OUT_CURP ((long long)(4LL * BN + NN))
#define OUT_REFR ((long long)(5LL * BN + NN))

#define ICH   16               // 4096 / 256 row chunks   (grid.y)
#define JCH   16               // 4096 / 256 col chunks   (grid.x)
#define PITCH 129              // 129 ≡ 1 (mod 32): rows AND cols conflict-free

// scratch (no dynamic allocation allowed)
__device__ __align__(16) float g_accP[ICH * BN];   // partials S@W_new
__device__ __align__(16) float g_accTP[JCH * BN];  // partials S@W_new^T

__device__ __forceinline__ float upd1(float w, float A, float Ai, float e, float ie)
{
    float sub = fmaxf(A * ie, Ai * e);        // 0 when row not paired-spiking
    float u = (w + C_BETA) - sub;
    u = fminf(fmaxf(u, 0.0f), 1.0f);
    return (w > 0.0f) ? u : w;                // sign_mask = W_rec > 0
}

// ---------------------------------------------------------------------------
// K1 (fused): phase 0 computes this block's row/col neuron data in smem,
// then the proven 256x256 tile pass: four 128x128 subtiles in (sj,si) order.
// Phase-B accumulators in registers per j-half; phase-C accumulators in smem
// across j-halves. 512 threads, 2 blocks/SM, 256 blocks.
// ---------------------------------------------------------------------------
__global__ void __launch_bounds__(512, 2) k_fused(
    const float* __restrict__ W, float* __restrict__ Wout,
    const float* __restrict__ mem_pot,
    const float* __restrict__ mem_pot_paired,
    const float* __restrict__ st)
{
    extern __shared__ float sm[];
    float*    c    = sm;                                 // [128][129]
    float*    cacc = sm + 128 * PITCH;                   // [32][256] accT acc
    float*    sA   = cacc + 32 * 256;                    // [256] row A
    float*    sAi  = sA + 256;                           // [256] row Ai
    float*    se   = sAi + 256;                          // [256] col e
    float*    sie  = se + 256;                           // [256] col ie
    unsigned* rbi  = (unsigned*)(sie + 256);             // [32][8] row words
    unsigned* rbj  = rbi + 256;                          // [32][8] col words

    const int jc   = blockIdx.x;       // 0..15
    const int ic   = blockIdx.y;       // 0..15
    const int tid  = threadIdx.x;
    const int warp = tid >> 5;         // 0..15
    const int lane = tid & 31;
    const int jg0  = jc * 256;
    const int igB  = ic * 256;
    const int lp   = lane * PITCH;

    // zero accT smem accumulators
    for (int k = tid; k < 32 * 256; k += 512) cacc[k] = 0.0f;

    // ---- Phase 0: per-neuron precompute for this block's rows and cols ----
    // threads 0..255 -> row neurons igB+t ; threads 256..511 -> col jg0+(t-256)
    {
        const bool isRow = tid < 256;
        const int  loc   = isRow ? tid : (tid - 256);
        const int  n     = (isRow ? igB : jg0) + loc;

        unsigned m = 0u;
        bool anyp = false;
#pragma unroll
        for (int b = 0; b < 32; ++b) {
            float mp = mem_pot[b * Nsz + n];
            if (mp > 1.0f) m |= (1u << b);
            float mpp = mem_pot_paired[b * Nsz + n];
            if (((mpp - 1.0f) - C_ALPHA) > 0.0f) anyp = true;
        }
        float stn = st[n];
        float maxst = (m == 0xffffffffu) ? C_TNOW
                    : (m ? fmaxf(C_TNOW, stn) : stn);
        float e  = expf(maxst * (1.0f / 50.0f));
        float ie = expf(-maxst * (1.0f / 50.0f));
        if (isRow) {
            sA[loc]  = anyp ? C_ALPHA * e  : 0.0f;
            sAi[loc] = anyp ? C_ALPHA * ie : 0.0f;
        } else {
            se[loc]  = e;
            sie[loc] = ie;
        }
        // transposed masks: warp g<8 -> row group g; warp 8+g -> col group g
        int g = warp & 7;
        unsigned* dst = (warp < 8) ? rbi : rbj;
#pragma unroll
        for (int b = 0; b < 32; ++b) {
            unsigned w = __ballot_sync(0xffffffffu, (m >> b) & 1u);
            if (lane == b) dst[b * 8 + g] = w;
        }
    }
    __syncthreads();   // phase-0 smem visible to all

    // Phase-B accumulators for the current j-half
    float aJ0, aJ1, aJ2, aJ3, bJ0, bJ1, bJ2, bJ3;

#pragma unroll
    for (int sj = 0; sj < 2; ++sj) {
        const int jg = jg0 + sj * 128;
        const int jl0 = sj * 128;

        // per-column exp factors for this j-half (from smem)
        float e0  = se[jl0 + lane];       float ie0 = sie[jl0 + lane];
        float e1  = se[jl0 + lane + 32];  float ie1 = sie[jl0 + lane + 32];
        float e2  = se[jl0 + lane + 64];  float ie2 = sie[jl0 + lane + 64];
        float e3  = se[jl0 + lane + 96];  float ie3 = sie[jl0 + lane + 96];

        aJ0 = aJ1 = aJ2 = aJ3 = 0.0f;
        bJ0 = bJ1 = bJ2 = bJ3 = 0.0f;

#pragma unroll
        for (int si = 0; si < 2; ++si) {
            const int ig0 = igB + si * 128;
            if (sj | si) __syncthreads();   // previous subtile fully consumed

            // ---- Phase A: update 8 contiguous rows per warp ----
#pragma unroll
            for (int r = 0; r < 8; ++r) {
                int il = warp * 8 + r;
                int ig = ig0 + il;
                float A  = sA[si * 128 + il];
                float Ai = sAi[si * 128 + il];
                const float* wr = W    + (size_t)ig * Nsz + jg;
                float*       wo = Wout + (size_t)ig * Nsz + jg;
                float w0 = wr[lane];
                float w1 = wr[lane + 32];
                float w2 = wr[lane + 64];
                float w3 = wr[lane + 96];
                float u0 = upd1(w0, A, Ai, e0, ie0);
                float u1 = upd1(w1, A, Ai, e1, ie1);
                float u2 = upd1(w2, A, Ai, e2, ie2);
                float u3 = upd1(w3, A, Ai, e3, ie3);
                wo[lane]      = u0;
                wo[lane + 32] = u1;
                wo[lane + 64] = u2;
                wo[lane + 96] = u3;
                float* cr = c + il * PITCH;
                cr[lane]      = u0;
                cr[lane + 32] = u1;
                cr[lane + 64] = u2;
                cr[lane + 96] = u3;
            }
            __syncthreads();

            // ---- Phase B: acc[b][j] over active rows (uniform ffs loop) ----
#pragma unroll
            for (int q = 0; q < 4; ++q) {
                unsigned m = rbi[warp * 8 + si * 4 + q];
                while (m) {
                    int r = q * 32 + __ffs(m) - 1; m &= m - 1;
                    const float* cr = c + r * PITCH;
                    aJ0 += cr[lane];
                    aJ1 += cr[lane + 32];
                    aJ2 += cr[lane + 64];
                    aJ3 += cr[lane + 96];
                }
            }
#pragma unroll
            for (int q = 0; q < 4; ++q) {
                unsigned m = rbi[(warp + 16) * 8 + si * 4 + q];
                while (m) {
                    int r = q * 32 + __ffs(m) - 1; m &= m - 1;
                    const float* cr = c + r * PITCH;
                    bJ0 += cr[lane];
                    bJ1 += cr[lane + 32];
                    bJ2 += cr[lane + 64];
                    bJ3 += cr[lane + 96];
                }
            }

            // ---- Phase C: accT[b][i] over active cols -> smem accumulator ----
            {
                float aI0 = 0, aI1 = 0, aI2 = 0, aI3 = 0;
                float bI0 = 0, bI1 = 0, bI2 = 0, bI3 = 0;
#pragma unroll
                for (int q = 0; q < 4; ++q) {
                    unsigned m = rbj[warp * 8 + sj * 4 + q];
                    while (m) {
                        int j = q * 32 + __ffs(m) - 1; m &= m - 1;
                        const float* cc = c + j + lp;
                        aI0 += cc[0];
                        aI1 += cc[32 * PITCH];
                        aI2 += cc[64 * PITCH];
                        aI3 += cc[96 * PITCH];
                    }
                }
#pragma unroll
                for (int q = 0; q < 4; ++q) {
                    unsigned m = rbj[(warp + 16) * 8 + sj * 4 + q];
                    while (m) {
                        int j = q * 32 + __ffs(m) - 1; m &= m - 1;
                        const float* cc = c + j + lp;
                        bI0 += cc[0];
                        bI1 += cc[32 * PITCH];
                        bI2 += cc[64 * PITCH];
                        bI3 += cc[96 * PITCH];
                    }
                }
                // fold into smem accT accumulator (warp-private rows, no races)
                float* pa = cacc + warp * 256 + si * 128 + lane;
                pa[0]  += aI0;
                pa[32] += aI1;
                pa[64] += aI2;
                pa[96] += aI3;
                float* pb = cacc + (warp + 16) * 256 + si * 128 + lane;
                pb[0]  += bI0;
                pb[32] += bI1;
                pb[64] += bI2;
                pb[96] += bI3;
            }
        }

        // write Phase-B partials for this j-half (one per ic chunk)
        {
            size_t oa = ((size_t)ic * Bsz + warp) * Nsz + jg + lane;
            g_accP[oa]      = aJ0;
            g_accP[oa + 32] = aJ1;
            g_accP[oa + 64] = aJ2;
            g_accP[oa + 96] = aJ3;
            size_t ob = ((size_t)ic * Bsz + warp + 16) * Nsz + jg + lane;
            g_accP[ob]      = bJ0;
            g_accP[ob + 32] = bJ1;
            g_accP[ob + 64] = bJ2;
            g_accP[ob + 96] = bJ3;
        }
    }

    // dump smem accT accumulator -> g_accTP[jc][b][igB + il]  (coalesced)
    __syncthreads();
#pragma unroll
    for (int k = 0; k < 16; ++k) {
        int idx = tid + 512 * k;          // 0..8191
        int b   = idx >> 8;
        int il  = idx & 255;
        g_accTP[((size_t)jc * Bsz + b) * Nsz + igB + il] = cacc[b * 256 + il];
    }
}

// ---------------------------------------------------------------------------
// K2: epilogue — reduce partials, integrate, leak, reset, refractory.
// S recomputed directly from mem_pot (no global mask array needed).
// ---------------------------------------------------------------------------
__global__ void __launch_bounds__(256) k_epilogue(
    const float* __restrict__ inp,
    const float* __restrict__ mem_pot,
    const float* __restrict__ mem_cur,
    const float* __restrict__ mem_pot_paired,
    const float* __restrict__ mem_cur_paired,
    const int*   __restrict__ refrac,
    float* __restrict__ out)
{
    int t = blockIdx.x * 256 + threadIdx.x;   // BN threads

    float acc = 0.0f;
#pragma unroll
    for (int cN = 0; cN < ICH; ++cN) acc += g_accP[(size_t)cN * BN + t];
    float accT = 0.0f;
#pragma unroll
    for (int cN = 0; cN < JCH; ++cN) accT += g_accTP[(size_t)cN * BN + t];

    int r  = refrac[t];
    int rd = (r > 0) ? (r - 1) : r;
    bool active = (rd == 0);

    float mp   = mem_pot[t];
    bool  s    = mp > 1.0f;                   // S = clip(ceil(mp-1),0,1)
    float mppv = mem_pot_paired[t];
    bool  sp   = ((mppv - 1.0f) - C_ALPHA) > 0.0f;

    float mc   = mem_cur[t];
    float mcpv = mem_cur_paired[t];

    float mcn  = active ? (inp[t] + acc) + mc : mc;
    float mcpn = active ? accT + mcpv : mcpv;
    float mpn  = active ? mcn + mp : mp;
    float mppn = active ? mcpn + mppv : mppv;

    mpn  *= C_INV_TAU_V;
    mcn  *= C_INV_TAU_I;
    mppn *= C_INV_TAU_V;
    mcpn *= C_INV_TAU_I;

    if (s)  mpn  = 0.0f;
    if (sp) mppn = 0.0f;
    float rn = s ? 2.0f : (float)rd;

    out[OUT_S    + t] = s ? 1.0f : 0.0f;
    out[OUT_POT  + t] = mpn;
    out[OUT_CUR  + t] = mcn;
    out[OUT_POTP + t] = mppn;
    out[OUT_CURP + t] = mcpn;
    out[OUT_REFR + t] = rn;
}

// ---------------------------------------------------------------------------
extern "C" void kernel_launch(void* const* d_in, const int* in_sizes, int n_in,
                              void* d_out, int out_size)
{
    const float* inp      = (const float*)d_in[0];
    const float* W_rec    = (const float*)d_in[1];
    const float* mem_pot  = (const float*)d_in[2];
    const float* mem_cur  = (const float*)d_in[3];
    const float* mpp      = (const float*)d_in[4];
    const float* mcp      = (const float*)d_in[5];
    const float* st       = (const float*)d_in[6];
    const int*   refrac   = (const int*)d_in[7];
    float* out = (float*)d_out;
    float* Wout = out + OUT_W;

    const int smem_bytes = (128 * PITCH + 32 * 256 + 4 * 256 + 512) * 4; // ~104.5 KB
    cudaFuncSetAttribute(k_fused, cudaFuncAttributeMaxDynamicSharedMemorySize,
                         smem_bytes);

    k_fused<<<dim3(JCH, ICH), 512, smem_bytes>>>(W_rec, Wout, mem_pot, mpp, st);
    k_epilogue<<<BN / 256, 256>>>(inp, mem_pot, mem_cur, mpp, mcp, refrac, out);
}